// round 15
// baseline (speedup 1.0000x reference)
#include <cuda_runtime.h>
#include <math.h>
#include <stdint.h>

// Problem constants
#define BSZ   32
#define SSEQ  512
#define HDIM  1024
#define G3H   3072                  // 3*H
#define MROWS (BSZ * SSEQ)          // 16384
#define HB    (BSZ * HDIM)          // 32768 floats per h buffer
#define RC    147                   // recurrent CTAs (one wave on 148 SMs)
#define UNITS 7                     // hidden units per CTA (147*7=1029>=1024, clamped)

// ---------------------------------------------------------------------------
// Scratch (static device globals — no allocation at kernel_launch time)
// ---------------------------------------------------------------------------
__device__ float g_gi[(size_t)SSEQ * G3H * BSZ];     // [t][j][b]  192 MB
__device__ float g_y0[(size_t)MROWS * HDIM];         // [b][s][h]   64 MB
// ping-pong hidden state, lane-packed: (hidx,b) at ((hidx>>2)*32+b)*4+(hidx&3)
__device__ __align__(16) float g_h[2][HB];
__device__ unsigned g_rbar;                          // grid-barrier counter

// ---------------------------------------------------------------------------
// f32x2 packed-FMA helpers (FFMA2 — exact fp32)
// ---------------------------------------------------------------------------
__device__ __forceinline__ void fma2(unsigned long long& d,
                                     unsigned long long a,
                                     unsigned long long b)
{
    asm("fma.rn.f32x2 %0, %1, %2, %3;" : "=l"(d) : "l"(a), "l"(b), "l"(d));
}
__device__ __forceinline__ float2 unpack2(unsigned long long v)
{
    float2 f;
    asm("mov.b64 {%0, %1}, %2;" : "=f"(f.x), "=f"(f.y) : "l"(v));
    return f;
}
// L1-bypassing loads (fresh data across the grid barrier)
__device__ __forceinline__ ulonglong2 ldcg_u64x2(const ulonglong2* p)
{
    ulonglong2 v;
    asm volatile("ld.global.cg.v2.u64 {%0,%1}, [%2];"
                 : "=l"(v.x), "=l"(v.y) : "l"(p));
    return v;
}
__device__ __forceinline__ float ldcg_f32(const float* p)
{
    float v;
    asm volatile("ld.global.cg.f32 %0, [%1];" : "=f"(v) : "l"(p));
    return v;
}

// ---------------------------------------------------------------------------
// GEMM: C[m][n] = sum_k A[m][k] * W[n][k] + bias[n]
// A row-major [16384,1024], W row-major [3072,1024]
// BM=128, BN=64, BK=16; 256 threads, 8x4 microtile (32 acc regs) so that
// 3 CTAs/SM fit (6 warps/SMSP — R13 showed 4 warps can't cover latency).
// A stored DUPLICATED in smem ({a,a} float2) so LDS.128 yields FFMA2-ready
// pairs directly: per kk = 16 FFMA2 + 5 LDS, zero packing MOVs.
// Epilogue scatters into gi[s][n][b], m = b*512 + s.
// ---------------------------------------------------------------------------
#define BM 128
#define BN 64
#define BK 16
#define AS2S 260    // padded float stride per k-row of duplicated A (256+4)
#define BSS  68     // padded float stride per k-row of B (64+4)

__global__ __launch_bounds__(256, 3)
void gemm_gi_kernel(const float* __restrict__ A,
                    const float* __restrict__ W,
                    const float* __restrict__ bias,
                    float* __restrict__ gi)
{
    __shared__ float As2[2 * BK * AS2S];   // 33280 B (duplicated A)
    __shared__ float Bs [2 * BK * BSS];    //  8704 B

    const int tid = threadIdx.x;
    const int tx = tid & 15;          // n microtile (4 n per thread)
    const int ty = tid >> 4;          // m microtile (8 m per thread)
    const int m0 = blockIdx.y * BM;
    const int n0 = blockIdx.x * BN;

    const int lrow = tid >> 2;            // 0..63
    const int lc4  = (tid & 3) * 4;       // 0,4,8,12

    const float* Ab = A + (size_t)(m0 + lrow) * HDIM + lc4;
    const float* Wb = W + (size_t)(n0 + lrow) * HDIM + lc4;

    float4 pa0 = *(const float4*)(Ab);
    float4 pa1 = *(const float4*)(Ab + (size_t)64 * HDIM);
    float4 pb  = *(const float4*)(Wb);

    unsigned long long acc2[8][2];
#pragma unroll
    for (int i = 0; i < 8; i++) { acc2[i][0] = 0ull; acc2[i][1] = 0ull; }

    // stage tile 0 into buffer 0
    {
        const float av0[4] = {pa0.x, pa0.y, pa0.z, pa0.w};
        const float av1[4] = {pa1.x, pa1.y, pa1.z, pa1.w};
        const float bv[4]  = {pb.x,  pb.y,  pb.z,  pb.w};
#pragma unroll
        for (int j = 0; j < 4; j++) {
            *(float2*)&As2[(lc4 + j) * AS2S + 2 * lrow]       = make_float2(av0[j], av0[j]);
            *(float2*)&As2[(lc4 + j) * AS2S + 2 * lrow + 128] = make_float2(av1[j], av1[j]);
            Bs[(lc4 + j) * BSS + lrow] = bv[j];
        }
    }
    __syncthreads();

    int buf = 0;
    for (int k0 = 0; k0 < HDIM; k0 += BK) {
        const bool nxt = (k0 + BK < HDIM);
        if (nxt) {
            pa0 = *(const float4*)(Ab + k0 + BK);
            pa1 = *(const float4*)(Ab + (size_t)64 * HDIM + k0 + BK);
            pb  = *(const float4*)(Wb + k0 + BK);
        }

        const float* ab = &As2[(size_t)buf * BK * AS2S + ty * 16];
        const float* bb = &Bs [(size_t)buf * BK * BSS  + tx * 4];
#pragma unroll
        for (int kk = 0; kk < BK; kk++) {
            const ulonglong2 aa01 = *(const ulonglong2*)(ab + (size_t)kk * AS2S + 0);
            const ulonglong2 aa23 = *(const ulonglong2*)(ab + (size_t)kk * AS2S + 4);
            const ulonglong2 aa45 = *(const ulonglong2*)(ab + (size_t)kk * AS2S + 8);
            const ulonglong2 aa67 = *(const ulonglong2*)(ab + (size_t)kk * AS2S + 12);
            const ulonglong2 bl   = *(const ulonglong2*)(bb + (size_t)kk * BSS);
            fma2(acc2[0][0], aa01.x, bl.x); fma2(acc2[0][1], aa01.x, bl.y);
            fma2(acc2[1][0], aa01.y, bl.x); fma2(acc2[1][1], aa01.y, bl.y);
            fma2(acc2[2][0], aa23.x, bl.x); fma2(acc2[2][1], aa23.x, bl.y);
            fma2(acc2[3][0], aa23.y, bl.x); fma2(acc2[3][1], aa23.y, bl.y);
            fma2(acc2[4][0], aa45.x, bl.x); fma2(acc2[4][1], aa45.x, bl.y);
            fma2(acc2[5][0], aa45.y, bl.x); fma2(acc2[5][1], aa45.y, bl.y);
            fma2(acc2[6][0], aa67.x, bl.x); fma2(acc2[6][1], aa67.x, bl.y);
            fma2(acc2[7][0], aa67.y, bl.x); fma2(acc2[7][1], aa67.y, bl.y);
        }

        if (nxt) {
            const int nb = buf ^ 1;
            const float av0[4] = {pa0.x, pa0.y, pa0.z, pa0.w};
            const float av1[4] = {pa1.x, pa1.y, pa1.z, pa1.w};
            const float bv[4]  = {pb.x,  pb.y,  pb.z,  pb.w};
            float* asd = &As2[(size_t)nb * BK * AS2S];
            float* bsd = &Bs [(size_t)nb * BK * BSS];
#pragma unroll
            for (int j = 0; j < 4; j++) {
                *(float2*)&asd[(lc4 + j) * AS2S + 2 * lrow]       = make_float2(av0[j], av0[j]);
                *(float2*)&asd[(lc4 + j) * AS2S + 2 * lrow + 128] = make_float2(av1[j], av1[j]);
                bsd[(lc4 + j) * BSS + lrow] = bv[j];
            }
            __syncthreads();
            buf = nb;
        }
    }

    // Epilogue: add bias, scatter to gi[t][j][b]
#pragma unroll
    for (int i = 0; i < 8; i++) {
        const int m = m0 + ty * 8 + i;
        const int b = m >> 9;           // m / 512
        const int s = m & 511;          // m % 512
#pragma unroll
        for (int j2 = 0; j2 < 2; j2++) {
            const float2 v = unpack2(acc2[i][j2]);
            const int n = n0 + tx * 4 + 2 * j2;
            gi[((size_t)s * G3H + n) * BSZ + b]     = v.x + bias[n];
            gi[((size_t)s * G3H + n + 1) * BSZ + b] = v.y + bias[n + 1];
        }
    }
}

// ---------------------------------------------------------------------------
// Persistent GRU recurrence: whole sequence in ONE launch.
// 147 CTAs x 512 threads. CTA owns 7 hidden units (21 gate rows); hidx
// clamped to 1023 — tail CTAs recompute identical values (bit-identical
// duplicate writes, benign). W_hh slice (84 KB) resident in smem.
// Warp w holds its 64-float h-chunk in registers; 21 rows as 10 pairs + 1.
// ---------------------------------------------------------------------------
__global__ __launch_bounds__(512)
void gru_seq_kernel(const float* __restrict__ Whh,   // [3H, H] row-major
                    const float* __restrict__ bhh,   // [3H]
                    const float* __restrict__ gi,    // [S][3H][B]
                    float* __restrict__ hbuf,        // 2*HB ping-pong (buf0 zeroed)
                    float* __restrict__ y_out)       // [B][S][H]
{
    extern __shared__ float smem[];
    float* sw   = smem;                        // [21][1024]   84 KB
    float* sred = smem + 21 * HDIM;            // [16][21][32] 42 KB

    const int tid  = threadIdx.x;
    const int lane = tid & 31;                 // batch b
    const int w    = tid >> 5;                 // warp 0..15
    const int bx   = blockIdx.x;

    // Load this CTA's 21 W_hh rows into smem (once for the whole sequence).
    for (int i = tid; i < 21 * (HDIM / 4); i += 512) {
        const int r  = i >> 8;                 // row 0..20  (= g*7 + u)
        const int c4 = (i & 255) * 4;
        const int g = r / 7, u = r - g * 7;
        int hidx = bx * 7 + u; if (hidx > HDIM - 1) hidx = HDIM - 1;
        *(float4*)&sw[(size_t)r * HDIM + c4] =
            *(const float4*)&Whh[((size_t)g * HDIM + hidx) * HDIM + c4];
    }
    __syncthreads();

    int hidx_f = bx * 7 + w; if (hidx_f > HDIM - 1) hidx_f = HDIM - 1; // valid w<7
    const int pk_f = ((hidx_f >> 2) * 32 + lane) * 4 + (hidx_f & 3);
    float bias_r = 0.f, bias_z = 0.f, bias_n = 0.f;
    if (w < 7) {
        bias_r = bhh[hidx_f];
        bias_z = bhh[HDIM + hidx_f];
        bias_n = bhh[2 * HDIM + hidx_f];
    }

    const int kq0 = w * 16;

    int cur = 0;
    for (int t = 0; t < SSEQ; ++t) {
        const float* h_in  = hbuf + (size_t)cur * HB;
        float*       h_out = hbuf + (size_t)(1 - cur) * HB;
        const ulonglong2* __restrict__ h2 = (const ulonglong2*)h_in;

        // --- early loads: gi[t] + h_prev (consumed after reduction sync) ---
        float ir = 0.f, iz = 0.f, inn = 0.f, hprev = 0.f;
        if (w < 7) {
            const float* git = gi + (size_t)t * G3H * BSZ;
            ir    = ldcg_f32(&git[(size_t)hidx_f * BSZ + lane]);
            iz    = ldcg_f32(&git[(size_t)(HDIM + hidx_f) * BSZ + lane]);
            inn   = ldcg_f32(&git[(size_t)(2 * HDIM + hidx_f) * BSZ + lane]);
            hprev = ldcg_f32(&h_in[pk_f]);
        }

        // --- load warp's h chunk (64 floats) into registers, L1-bypassing ---
        ulonglong2 hreg[16];
#pragma unroll
        for (int i = 0; i < 16; ++i)
            hreg[i] = ldcg_u64x2(&h2[(kq0 + i) * 32 + lane]);

        // --- 10 row-pairs + 1 single row; 4 (2) live accumulator chains ---
        const float* wbase = sw + 4 * kq0;
#pragma unroll 2
        for (int rp = 0; rp < 10; ++rp) {
            const float* wp0 = wbase + (size_t)(2 * rp) * HDIM;
            const float* wp1 = wp0 + HDIM;
            unsigned long long a0 = 0ull, a1 = 0ull, b0 = 0ull, b1 = 0ull;
#pragma unroll
            for (int i = 0; i < 16; ++i) {
                const ulonglong2 w0 = *(const ulonglong2*)(wp0 + 4 * i);
                const ulonglong2 w1 = *(const ulonglong2*)(wp1 + 4 * i);
                fma2(a0, w0.x, hreg[i].x);
                fma2(a1, w0.y, hreg[i].y);
                fma2(b0, w1.x, hreg[i].x);
                fma2(b1, w1.y, hreg[i].y);
            }
            const float2 fa0 = unpack2(a0), fa1 = unpack2(a1);
            const float2 fb0 = unpack2(b0), fb1 = unpack2(b1);
            sred[((size_t)w * 21 + 2 * rp) * 32 + lane]     = (fa0.x + fa0.y) + (fa1.x + fa1.y);
            sred[((size_t)w * 21 + 2 * rp + 1) * 32 + lane] = (fb0.x + fb0.y) + (fb1.x + fb1.y);
        }
        {   // row 20
            const float* wp = wbase + (size_t)20 * HDIM;
            unsigned long long a0 = 0ull, a1 = 0ull;
#pragma unroll
            for (int i = 0; i < 16; ++i) {
                const ulonglong2 w0 = *(const ulonglong2*)(wp + 4 * i);
                fma2(a0, w0.x, hreg[i].x);
                fma2(a1, w0.y, hreg[i].y);
            }
            const float2 fa0 = unpack2(a0), fa1 = unpack2(a1);
            sred[((size_t)w * 21 + 20) * 32 + lane] = (fa0.x + fa0.y) + (fa1.x + fa1.y);
        }
        __syncthreads();

        // ---- finalize: thread (u=w<7, b=lane) produces h[hidx_f][b] ----
        if (w < 7) {
            float gr = bias_r, gz = bias_z, gn = bias_n;
#pragma unroll
            for (int ww = 0; ww < 16; ++ww) {
                gr += sred[((size_t)ww * 21 + 0 * 7 + w) * 32 + lane];
                gz += sred[((size_t)ww * 21 + 1 * 7 + w) * 32 + lane];
                gn += sred[((size_t)ww * 21 + 2 * 7 + w) * 32 + lane];
            }
            const float r_ = 1.0f / (1.0f + expf(-(ir + gr)));
            const float z_ = 1.0f / (1.0f + expf(-(iz + gz)));
            const float n_ = tanhf(inn + r_ * gn);
            const float hn = (1.0f - z_) * n_ + z_ * hprev;

            h_out[pk_f] = hn;                                   // dup CTAs: same bits
            y_out[((size_t)lane * SSEQ + t) * HDIM + hidx_f] = hn;
        }
        __syncthreads();            // all stores program-ordered before arrive

        // ---- grid barrier (release/acquire on monotonic counter) ----
        if (t != SSEQ - 1) {
            if (tid == 0) {
                const unsigned tgt = (unsigned)(t + 1) * RC;
                unsigned* bar = &g_rbar;
                asm volatile("red.release.gpu.add.u32 [%0], %1;"
                             :: "l"(bar), "r"(1u) : "memory");
                unsigned v;
                for (;;) {
                    asm volatile("ld.acquire.gpu.u32 %0, [%1];"
                                 : "=r"(v) : "l"(bar) : "memory");
                    if (v >= tgt) break;
                    __nanosleep(16);
                }
            }
            __syncthreads();
        }
        cur ^= 1;
    }
}

// ---------------------------------------------------------------------------
__global__ void zero_h_kernel(float* __restrict__ h)
{
    const int i = blockIdx.x * 256 + threadIdx.x;
    if (i < HB) h[i] = 0.0f;
    if (i == 0) g_rbar = 0u;        // reset barrier counter (deterministic replays)
}

// h_n[0] = y0[:, S-1, :], h_n[1] = y1[:, S-1, :]
__global__ void copy_hn_kernel(const float* __restrict__ y0,
                               const float* __restrict__ y1,
                               float* __restrict__ outhn)
{
    const int i = blockIdx.x * 256 + threadIdx.x;   // 0 .. 2*B*H-1
    if (i >= 2 * HB) return;
    const int half = HB;
    if (i < half) {
        const int b = i >> 10, h = i & 1023;
        outhn[i] = y0[((size_t)b * SSEQ + (SSEQ - 1)) * HDIM + h];
    } else {
        const int j = i - half;
        const int b = j >> 10, h = j & 1023;
        outhn[i] = y1[((size_t)b * SSEQ + (SSEQ - 1)) * HDIM + h];
    }
}

// ---------------------------------------------------------------------------
extern "C" void kernel_launch(void* const* d_in, const int* in_sizes, int n_in,
                              void* d_out, int out_size)
{
    const float* x    = (const float*)d_in[0];
    const float* Wih0 = (const float*)d_in[1];
    const float* bih0 = (const float*)d_in[2];
    const float* Whh0 = (const float*)d_in[3];
    const float* bhh0 = (const float*)d_in[4];
    const float* Wih1 = (const float*)d_in[5];
    const float* bih1 = (const float*)d_in[6];
    const float* Whh1 = (const float*)d_in[7];
    const float* bhh1 = (const float*)d_in[8];
    float* out = (float*)d_out;

    float* gi;  cudaGetSymbolAddress((void**)&gi,  g_gi);
    float* y0;  cudaGetSymbolAddress((void**)&y0,  g_y0);
    float* hb;  cudaGetSymbolAddress((void**)&hb,  g_h);

    const int SMEM_REC = (21 * HDIM + 16 * 21 * 32) * (int)sizeof(float); // 129024
    static int smem_set = 0;
    if (!smem_set) {
        cudaFuncSetAttribute(gru_seq_kernel,
                             cudaFuncAttributeMaxDynamicSharedMemorySize, SMEM_REC);
        smem_set = 1;
    }

    const dim3 gemm_grid(G3H / BN, MROWS / BM);   // (48, 128)

    // ---- Layer 0 ----
    gemm_gi_kernel<<<gemm_grid, 256>>>(x, Wih0, bih0, gi);
    zero_h_kernel<<<(HB + 255) / 256, 256>>>(hb);
    gru_seq_kernel<<<RC, 512, SMEM_REC>>>(Whh0, bhh0, gi, hb, y0);

    // ---- Layer 1 ----
    gemm_gi_kernel<<<gemm_grid, 256>>>(y0, Wih1, bih1, gi);
    zero_h_kernel<<<(HB + 255) / 256, 256>>>(hb);
    gru_seq_kernel<<<RC, 512, SMEM_REC>>>(Whh1, bhh1, gi, hb, out);

    // ---- h_n tail (only if the harness output includes it) ----
    const long long need = (long long)MROWS * HDIM + 2LL * HB;
    if ((long long)out_size >= need) {
        copy_hn_kernel<<<(2 * HB + 255) / 256, 256>>>(y0, out, out + (size_t)MROWS * HDIM);
    }
}